// round 12
// baseline (speedup 1.0000x reference)
#include <cuda_runtime.h>
#include <math.h>

// Problem constants
#define BB 16
#define NPIX (288 * 800)        // 230400 pixels per batch per plane
#define NVEC (NPIX / 4)         // 57600 float4 groups per plane per batch
#define TPB 256
#define NL 4                    // tracked labels 1..4 (label 0 stats dead)
#define DELTA_V 0.5f

// Pass 1 geometry (proven R11 config)
#define BPB1 45                 // blocks per batch -> 720 total, 5/SM
#define KIT1 5                  // 45*256*5 = 57600 exactly
#define NP1 21                  // 16 sums + 4 counts + wnll

// Pass 2 geometry: 4 blocks/SM, balanced single wave
#define BPB2 37                 // 37*16 = 592 = 4 * 148 SMs
#define GB2  (BPB2 * BB)        // 592
#define PTH2 (BPB2 * TPB)       // 9472 threads per batch
#define KIT2 6                  // 6*9472 = 56832 main groups
#define REM2 (NVEC - KIT2 * PTH2)  // 768 remainder groups

// Scratch (device globals; allocation is forbidden)
__device__ float g_p1[BB][BPB1][NP1];  // pass1 per-block partials
__device__ float g_p2[BB][BPB2];       // pass2 per-block hvar partial
__device__ float g_cnts[BB][NL];       // written by pass2 blk==0 of each batch
__device__ float g_wnll[BB];           // written by pass2 blk==0 of each batch
__device__ int   g_t2;                 // finalize ticket (reset each replay)

__device__ __forceinline__ float warp_sum(float v) {
    #pragma unroll
    for (int o = 16; o > 0; o >>= 1) v += __shfl_xor_sync(0xffffffffu, v, o);
    return v;
}

// ---------------------------------------------------------------------------
// Pass 1: per-(b,label) embedding sums + counts + weighted CE.
// grid=(45,16), block=256, 5 blocks/SM.  (Unchanged from R11.)
__global__ void __launch_bounds__(TPB, 5)
pass1_kernel(const float* __restrict__ emb,
             const float* __restrict__ seg2,
             const int*   __restrict__ lab) {
    const int b   = blockIdx.y;
    const int blk = blockIdx.x;
    const int tid = threadIdx.x;
    const float* e0 = emb  + (size_t)b * 4 * NPIX;
    const float* s0 = seg2 + (size_t)b * 2 * NPIX;
    const int*   l0 = lab  + (size_t)b * NPIX;
    const int base = blk * (TPB * KIT1) + tid;

    float acc[NL][4];
    float cnt[NL];
    #pragma unroll
    for (int l = 0; l < NL; l++) {
        cnt[l] = 0.f;
        #pragma unroll
        for (int d = 0; d < 4; d++) acc[l][d] = 0.f;
    }
    float wnll = 0.f;

    #pragma unroll
    for (int k = 0; k < KIT1; k++) {
        const int i = base + k * TPB;
        float4 e0v = __ldg((const float4*)(e0)          + i);
        float4 e1v = __ldg((const float4*)(e0 + NPIX)   + i);
        float4 e2v = __ldg((const float4*)(e0 + 2*NPIX) + i);
        float4 e3v = __ldg((const float4*)(e0 + 3*NPIX) + i);
        int4   lv  = __ldg((const int4*)(l0) + i);
        float4 g0v = __ldg((const float4*)(s0)          + i);
        float4 g1v = __ldg((const float4*)(s0 + NPIX)   + i);

        const float ed0[4] = {e0v.x, e0v.y, e0v.z, e0v.w};
        const float ed1[4] = {e1v.x, e1v.y, e1v.z, e1v.w};
        const float ed2[4] = {e2v.x, e2v.y, e2v.z, e2v.w};
        const float ed3[4] = {e3v.x, e3v.y, e3v.z, e3v.w};
        const int   lbs[4] = {lv.x, lv.y, lv.z, lv.w};
        const float ga[4]  = {g0v.x, g0v.y, g0v.z, g0v.w};
        const float gb[4]  = {g1v.x, g1v.y, g1v.z, g1v.w};

        #pragma unroll
        for (int p = 0; p < 4; p++) {
            const int L = lbs[p];
            #pragma unroll
            for (int l = 0; l < NL; l++) {
                if (L == l + 1) {
                    acc[l][0] += ed0[p];
                    acc[l][1] += ed1[p];
                    acc[l][2] += ed2[p];
                    acc[l][3] += ed3[p];
                    cnt[l]    += 1.f;
                }
            }
            // weighted binary CE: nll = softplus(tgt ? (a-c) : (c-a))
            const float d  = ga[p] - gb[p];
            const float ax = fabsf(d);
            const int tgt  = (L > 0);
            const float hinge = tgt ? fmaxf(d, 0.f) : fmaxf(-d, 0.f);
            const float sp = hinge + __logf(1.0f + __expf(-ax));
            wnll += (tgt ? 1.0f : 0.5f) * sp;
        }
    }

    // block reduce 21 values -> per-block partial
    __shared__ float sh[TPB / 32][NP1];
    const int wid = tid >> 5, lane = tid & 31;
    float vals[NP1];
    #pragma unroll
    for (int l = 0; l < NL; l++) {
        #pragma unroll
        for (int d = 0; d < 4; d++) vals[l * 4 + d] = acc[l][d];
        vals[16 + l] = cnt[l];
    }
    vals[20] = wnll;
    #pragma unroll
    for (int j = 0; j < NP1; j++) {
        float r = warp_sum(vals[j]);
        if (lane == 0) sh[wid][j] = r;
    }
    __syncthreads();
    if (tid < NP1) {
        float s = 0.f;
        #pragma unroll
        for (int w = 0; w < TPB / 32; w++) s += sh[w][tid];
        g_p1[b][blk][tid] = s;
    }
}

// ---------------------------------------------------------------------------
// Pass 2: branchless hinge, 2-group load batching (10 LDG.128 in flight),
// 4 blocks/SM (64-reg budget), balanced single wave 592 blocks.
__global__ void __launch_bounds__(TPB, 4)
pass2_kernel(const float* __restrict__ emb,
             const int*   __restrict__ lab,
             float* __restrict__ out) {
    const int b   = blockIdx.y;
    const int blk = blockIdx.x;
    const int tid = threadIdx.x;
    const float* e0 = emb + (size_t)b * 4 * NPIX;
    const int*   l0 = lab + (size_t)b * NPIX;
    const int base = blk * TPB + tid;           // [0, 9472)

    // ---- reduce this batch's pass1 partials -> label tables ----
    __shared__ float red[NP1][8];
    __shared__ float tot[NP1];
    __shared__ float4 smu[NL + 1];   // [0] = zeros (background)
    __shared__ float  sinv[NL + 1];  // [0] = 0
    if (tid < NP1 * 8) {
        const int col = tid >> 3, sub = tid & 7;
        float s = 0.f;
        for (int p = sub; p < BPB1; p += 8) s += g_p1[b][p][col];
        red[col][sub] = s;
    }
    __syncthreads();
    if (tid < NP1) {
        float s = 0.f;
        #pragma unroll
        for (int u = 0; u < 8; u++) s += red[tid][u];
        tot[tid] = s;
    }
    __syncthreads();
    if (tid <= NL) {
        if (tid == 0) {
            smu[0] = make_float4(0.f, 0.f, 0.f, 0.f);
            sinv[0] = 0.f;
        } else {
            const int l = tid - 1;
            const float c = tot[16 + l];
            const float inv = 1.0f / fmaxf(c, 1.0f);
            smu[tid] = make_float4(tot[l * 4 + 0] * inv, tot[l * 4 + 1] * inv,
                                   tot[l * 4 + 2] * inv, tot[l * 4 + 3] * inv);
            sinv[tid] = (c > 0.f) ? inv : 0.f;
            if (blk == 0) g_cnts[b][l] = c;
        }
        if (blk == 0 && tid == 0) g_wnll[b] = tot[20];
    }
    __syncthreads();

    // ---- main loop: 3 pairs of groups, all 10 loads issued up front ----
    float hvar = 0.f;

    #pragma unroll
    for (int kp = 0; kp < KIT2 / 2; kp++) {
        const int i0 = base + (2 * kp)     * PTH2;
        const int i1 = base + (2 * kp + 1) * PTH2;
        float4 a0 = __ldg((const float4*)(e0)          + i0);
        float4 a1 = __ldg((const float4*)(e0 + NPIX)   + i0);
        float4 a2 = __ldg((const float4*)(e0 + 2*NPIX) + i0);
        float4 a3 = __ldg((const float4*)(e0 + 3*NPIX) + i0);
        int4   al = __ldg((const int4*)(l0) + i0);
        float4 b0 = __ldg((const float4*)(e0)          + i1);
        float4 b1 = __ldg((const float4*)(e0 + NPIX)   + i1);
        float4 b2 = __ldg((const float4*)(e0 + 2*NPIX) + i1);
        float4 b3 = __ldg((const float4*)(e0 + 3*NPIX) + i1);
        int4   bl = __ldg((const int4*)(l0) + i1);

        {
            const float ed0[4] = {a0.x, a0.y, a0.z, a0.w};
            const float ed1[4] = {a1.x, a1.y, a1.z, a1.w};
            const float ed2[4] = {a2.x, a2.y, a2.z, a2.w};
            const float ed3[4] = {a3.x, a3.y, a3.z, a3.w};
            const int   lbs[4] = {al.x, al.y, al.z, al.w};
            #pragma unroll
            for (int p = 0; p < 4; p++) {
                const int L = lbs[p];
                const float4 mu = smu[L];
                const float w   = sinv[L];
                const float d0 = ed0[p] - mu.x;
                const float d1 = ed1[p] - mu.y;
                const float d2 = ed2[p] - mu.z;
                const float d3 = ed3[p] - mu.w;
                const float sq = d0*d0 + d1*d1 + d2*d2 + d3*d3;
                const float t = fmaxf(sqrtf(sq) - DELTA_V, 0.0f);
                hvar = fmaf(t * t, w, hvar);
            }
        }
        {
            const float ed0[4] = {b0.x, b0.y, b0.z, b0.w};
            const float ed1[4] = {b1.x, b1.y, b1.z, b1.w};
            const float ed2[4] = {b2.x, b2.y, b2.z, b2.w};
            const float ed3[4] = {b3.x, b3.y, b3.z, b3.w};
            const int   lbs[4] = {bl.x, bl.y, bl.z, bl.w};
            #pragma unroll
            for (int p = 0; p < 4; p++) {
                const int L = lbs[p];
                const float4 mu = smu[L];
                const float w   = sinv[L];
                const float d0 = ed0[p] - mu.x;
                const float d1 = ed1[p] - mu.y;
                const float d2 = ed2[p] - mu.z;
                const float d3 = ed3[p] - mu.w;
                const float sq = d0*d0 + d1*d1 + d2*d2 + d3*d3;
                const float t = fmaxf(sqrtf(sq) - DELTA_V, 0.0f);
                hvar = fmaf(t * t, w, hvar);
            }
        }
    }
    // remainder: 768 single groups
    if (base < REM2) {
        const int i = KIT2 * PTH2 + base;
        float4 a0 = __ldg((const float4*)(e0)          + i);
        float4 a1 = __ldg((const float4*)(e0 + NPIX)   + i);
        float4 a2 = __ldg((const float4*)(e0 + 2*NPIX) + i);
        float4 a3 = __ldg((const float4*)(e0 + 3*NPIX) + i);
        int4   al = __ldg((const int4*)(l0) + i);
        const float ed0[4] = {a0.x, a0.y, a0.z, a0.w};
        const float ed1[4] = {a1.x, a1.y, a1.z, a1.w};
        const float ed2[4] = {a2.x, a2.y, a2.z, a2.w};
        const float ed3[4] = {a3.x, a3.y, a3.z, a3.w};
        const int   lbs[4] = {al.x, al.y, al.z, al.w};
        #pragma unroll
        for (int p = 0; p < 4; p++) {
            const int L = lbs[p];
            const float4 mu = smu[L];
            const float w   = sinv[L];
            const float d0 = ed0[p] - mu.x;
            const float d1 = ed1[p] - mu.y;
            const float d2 = ed2[p] - mu.z;
            const float d3 = ed3[p] - mu.w;
            const float sq = d0*d0 + d1*d1 + d2*d2 + d3*d3;
            const float t = fmaxf(sqrtf(sq) - DELTA_V, 0.0f);
            hvar = fmaf(t * t, w, hvar);
        }
    }

    // block reduce 1 value -> per-block partial
    {
        __shared__ float shh[TPB / 32];
        const int wid = tid >> 5, lane = tid & 31;
        float r = warp_sum(hvar);
        if (lane == 0) shh[wid] = r;
        __syncthreads();
        if (tid == 0) {
            float s = 0.f;
            #pragma unroll
            for (int w = 0; w < TPB / 32; w++) s += shh[w];
            g_p2[b][blk] = s;
        }
    }

    // ---- finalize in the last block (ticket; no waiting => no deadlock) ----
    __shared__ int sh_last;
    __threadfence();
    __syncthreads();
    if (tid == 0) sh_last = (atomicAdd(&g_t2, 1) == GB2 - 1);
    __syncthreads();
    if (!sh_last) return;

    __shared__ float fin[BB];
    if (tid < BB) {
        float s = 0.f;
        #pragma unroll
        for (int p = 0; p < BPB2; p++) s += g_p2[tid][p];
        fin[tid] = s;
    }
    __syncthreads();
    if (tid == 0) {
        float var_tot = 0.f, wn = 0.f, cfg = 0.f;
        #pragma unroll
        for (int bb = 0; bb < BB; bb++) {
            float nlanes = 0.f;
            #pragma unroll
            for (int l = 0; l < NL; l++) {
                const float c = g_cnts[bb][l];
                if (c > 0.f) nlanes += 1.f;
                cfg += c;
            }
            var_tot += fin[bb] / fmaxf(nlanes, 1.f);
            wn += g_wnll[bb];
        }
        const float wsum = 0.5f * (float)(BB * NPIX) + 0.5f * cfg;
        // dist_loss == 0 identically (delta_d added to all pair distances);
        // reg_loss == 0.  loss = seg_ce + var.
        out[0] = wn / wsum + var_tot / (float)BB;
        g_t2 = 0;   // reset for the next graph replay
    }
}

// ---------------------------------------------------------------------------
extern "C" void kernel_launch(void* const* d_in, const int* in_sizes, int n_in,
                              void* d_out, int out_size) {
    const float* emb  = (const float*)d_in[0];  // [16,4,288,800] f32
    const float* bseg = (const float*)d_in[1];  // [16,2,288,800] f32
    const int*   lab  = (const int*)  d_in[2];  // [16,288,800]   i32
    float* out = (float*)d_out;
    (void)in_sizes; (void)n_in; (void)out_size;

    dim3 grid1(BPB1, BB);
    dim3 grid2(BPB2, BB);
    pass1_kernel<<<grid1, TPB>>>(emb, bseg, lab);
    pass2_kernel<<<grid2, TPB>>>(emb, lab, out);
}

// round 15
// speedup vs baseline: 1.0971x; 1.0971x over previous
#include <cuda_runtime.h>
#include <cuda_bf16.h>
#include <math.h>

// Problem constants
#define BB 16
#define NPIX (288 * 800)        // 230400 pixels per batch per plane
#define NVEC (NPIX / 4)         // 57600 float4 groups per batch
#define BPB 9                   // blocks per batch
#define GB  (BPB * BB)          // 144 blocks <= 148 SMs -> 1/SM, all resident
#define TPB 1024
#define NWARP (TPB / 32)        // 32
#define GPB (NVEC / BPB)        // 6400 groups per block
#define KIT 6                   // 6*1024 = 6144 main groups per block
#define REM (GPB - KIT * TPB)   // 256 remainder groups
#define NL 4                    // labels 1..4 (label 0 stats dead)
#define NP1 21                  // 16 sums + 4 counts + wnll
#define DELTA_V 0.5f

// Dynamic smem: 25600 pixels * 8 B (bf16x4) + 6400 groups * 2 B (nibble labels)
#define SE_SLOTS 25600
#define DYN_SMEM (SE_SLOTS * 8 + GPB * 2)   // 217600 B

// Scratch (device globals; allocation is forbidden). Zero-initialized at load.
__device__ float  g_p1[BB][BPB][NP1];   // phase1 per-block partials
__device__ float  g_p2[BB][BPB];        // phase2 per-block hvar partials
__device__ float4 g_mu[BB][NL + 1];     // centroid tables ([0] stays zero)
__device__ float  g_inv[BB][NL + 1];    // 1/count tables ([0] stays zero)
__device__ float  g_cnts[BB][NL];
__device__ float  g_wnll[BB];
__device__ int    g_tb[BB];             // per-batch phase1 tickets
__device__ int    g_flag[BB];           // per-batch means-ready flags
__device__ int    g_t2;                 // global finalize ticket

__device__ __forceinline__ float warp_sum(float v) {
    #pragma unroll
    for (int o = 16; o > 0; o >>= 1) v += __shfl_xor_sync(0xffffffffu, v, o);
    return v;
}

// smem slot for (iter k, pixel-in-group p, thread t): [k][p][t] layout,
// remainder iter (k==KIT) compacted to 256-thread stride.
__device__ __forceinline__ int se_slot(int k, int p, int t) {
    return (k < KIT) ? (k * (4 * TPB) + p * TPB + t)
                     : (KIT * (4 * TPB) + p * REM + t);
}
__device__ __forceinline__ int lab_slot(int k, int t) {
    return (k < KIT) ? (k * TPB + t) : (KIT * TPB + t);
}

// ---------------------------------------------------------------------------
// Single-DRAM-pass fused kernel. grid=(9,16)=144 blocks of 1024 threads,
// 217.6 KB dynamic smem => exactly 1 block/SM => all blocks co-resident
// => per-batch spin barrier is deadlock-free by construction.
__global__ void __launch_bounds__(TPB, 1)
fused_kernel(const float* __restrict__ emb,
             const float* __restrict__ seg2,
             const int*   __restrict__ lab,
             float* __restrict__ out) {
    extern __shared__ char dynsmem[];
    uint2*          se   = (uint2*)dynsmem;                    // bf16x4 pixels
    unsigned short* slab = (unsigned short*)(dynsmem + SE_SLOTS * 8);

    const int b   = blockIdx.y;
    const int blk = blockIdx.x;          // 0..8
    const int tid = threadIdx.x;
    const float* e0 = emb  + (size_t)b * 4 * NPIX;
    const float* s0 = seg2 + (size_t)b * 2 * NPIX;
    const int*   l0 = lab  + (size_t)b * NPIX;
    const int gbase = blk * GPB;         // batch-local group base for block

    // ================= Phase 1: stream + stats + pack to smem ==============
    float acc[NL][4];
    float cnt[NL];
    #pragma unroll
    for (int l = 0; l < NL; l++) {
        cnt[l] = 0.f;
        #pragma unroll
        for (int d = 0; d < 4; d++) acc[l][d] = 0.f;
    }
    float wnll = 0.f;

    #pragma unroll
    for (int k = 0; k <= KIT; k++) {
        if (k == KIT && tid >= REM) break;
        const int j = (k < KIT) ? (k * TPB + tid) : (KIT * TPB + tid);
        const int i = gbase + j;          // batch-local group index

        float4 e0v = __ldg((const float4*)(e0)          + i);
        float4 e1v = __ldg((const float4*)(e0 + NPIX)   + i);
        float4 e2v = __ldg((const float4*)(e0 + 2*NPIX) + i);
        float4 e3v = __ldg((const float4*)(e0 + 3*NPIX) + i);
        int4   lv  = __ldg((const int4*)(l0) + i);
        float4 g0v = __ldg((const float4*)(s0)          + i);
        float4 g1v = __ldg((const float4*)(s0 + NPIX)   + i);

        const float ed0[4] = {e0v.x, e0v.y, e0v.z, e0v.w};
        const float ed1[4] = {e1v.x, e1v.y, e1v.z, e1v.w};
        const float ed2[4] = {e2v.x, e2v.y, e2v.z, e2v.w};
        const float ed3[4] = {e3v.x, e3v.y, e3v.z, e3v.w};
        const int   lbs[4] = {lv.x, lv.y, lv.z, lv.w};
        const float ga[4]  = {g0v.x, g0v.y, g0v.z, g0v.w};
        const float gb[4]  = {g1v.x, g1v.y, g1v.z, g1v.w};

        #pragma unroll
        for (int p = 0; p < 4; p++) {
            const int L = lbs[p];
            #pragma unroll
            for (int l = 0; l < NL; l++) {
                if (L == l + 1) {
                    acc[l][0] += ed0[p];
                    acc[l][1] += ed1[p];
                    acc[l][2] += ed2[p];
                    acc[l][3] += ed3[p];
                    cnt[l]    += 1.f;
                }
            }
            // weighted binary CE: nll = softplus(tgt ? (a-c) : (c-a))
            const float d  = ga[p] - gb[p];
            const float ax = fabsf(d);
            const int tgt  = (L > 0);
            const float hinge = tgt ? fmaxf(d, 0.f) : fmaxf(-d, 0.f);
            const float sp = hinge + __logf(1.0f + __expf(-ax));
            wnll += (tgt ? 1.0f : 0.5f) * sp;

            // pack pixel to bf16x4 in smem ([k][p][t] layout, conflict-free)
            __nv_bfloat162 h01 = __floats2bfloat162_rn(ed0[p], ed1[p]);
            __nv_bfloat162 h23 = __floats2bfloat162_rn(ed2[p], ed3[p]);
            uint2 pk;
            pk.x = *reinterpret_cast<unsigned int*>(&h01);
            pk.y = *reinterpret_cast<unsigned int*>(&h23);
            se[se_slot(k, p, tid)] = pk;
        }
        // nibble-pack the 4 labels (values 0..4 fit in 4 bits)
        slab[lab_slot(k, tid)] =
            (unsigned short)(lbs[0] | (lbs[1] << 4) | (lbs[2] << 8) | (lbs[3] << 12));
    }

    // block reduce 21 values -> per-block partial
    {
        __shared__ float sh[NWARP][NP1];
        const int wid = tid >> 5, lane = tid & 31;
        float vals[NP1];
        #pragma unroll
        for (int l = 0; l < NL; l++) {
            #pragma unroll
            for (int d = 0; d < 4; d++) vals[l * 4 + d] = acc[l][d];
            vals[16 + l] = cnt[l];
        }
        vals[20] = wnll;
        #pragma unroll
        for (int j = 0; j < NP1; j++) {
            float r = warp_sum(vals[j]);
            if (lane == 0) sh[wid][j] = r;
        }
        __syncthreads();
        if (tid < NP1) {
            float s = 0.f;
            #pragma unroll
            for (int w = 0; w < NWARP; w++) s += sh[w][tid];
            g_p1[b][blk][tid] = s;
        }
    }

    // ============ Per-batch barrier: last of 9 blocks builds tables =========
    __shared__ int sh_last;
    __threadfence();
    __syncthreads();
    if (tid == 0) sh_last = (atomicAdd(&g_tb[b], 1) == BPB - 1);
    __syncthreads();

    if (sh_last) {
        __shared__ float tot[NP1];
        if (tid < NP1) {
            float s = 0.f;
            #pragma unroll
            for (int p = 0; p < BPB; p++) s += g_p1[b][p][tid];
            tot[tid] = s;
        }
        __syncthreads();
        if (tid < NL) {                  // table entries 1..4; entry 0 stays 0
            const int l = tid;
            const float c = tot[16 + l];
            const float inv = 1.0f / fmaxf(c, 1.0f);
            g_mu[b][l + 1] = make_float4(tot[l*4+0] * inv, tot[l*4+1] * inv,
                                         tot[l*4+2] * inv, tot[l*4+3] * inv);
            g_inv[b][l + 1] = (c > 0.f) ? inv : 0.f;
            g_cnts[b][l] = c;
        }
        if (tid == NL) g_wnll[b] = tot[20];
        __threadfence();
        __syncthreads();
        if (tid == 0) *(volatile int*)&g_flag[b] = 1;
    } else {
        if (tid == 0) {
            while (*(volatile int*)&g_flag[b] == 0) __nanosleep(64);
        }
        __syncthreads();
        __threadfence();
    }

    // ============ Phase 2: hinge entirely from SMEM (no global reads) =======
    __shared__ float4 smu[NL + 1];
    __shared__ float  sinv[NL + 1];
    if (tid <= NL) {
        smu[tid]  = g_mu[b][tid];
        sinv[tid] = g_inv[b][tid];
    }
    __syncthreads();

    float hvar = 0.f;
    #pragma unroll
    for (int k = 0; k <= KIT; k++) {
        if (k == KIT && tid >= REM) break;
        const unsigned short ls = slab[lab_slot(k, tid)];
        #pragma unroll
        for (int p = 0; p < 4; p++) {
            const uint2 pk = se[se_slot(k, p, tid)];
            __nv_bfloat162 h01 = *reinterpret_cast<const __nv_bfloat162*>(&pk.x);
            __nv_bfloat162 h23 = *reinterpret_cast<const __nv_bfloat162*>(&pk.y);
            float2 f01 = __bfloat1622float2(h01);
            float2 f23 = __bfloat1622float2(h23);
            const int L = (ls >> (p * 4)) & 0xF;      // 0..4 table index
            const float4 mu = smu[L];
            const float w   = sinv[L];
            const float d0 = f01.x - mu.x;
            const float d1 = f01.y - mu.y;
            const float d2 = f23.x - mu.z;
            const float d3 = f23.y - mu.w;
            const float sq = d0*d0 + d1*d1 + d2*d2 + d3*d3;
            const float t = fmaxf(sqrtf(sq) - DELTA_V, 0.0f);
            hvar = fmaf(t * t, w, hvar);
        }
    }

    {
        __shared__ float shh[NWARP];
        const int wid = tid >> 5, lane = tid & 31;
        float r = warp_sum(hvar);
        if (lane == 0) shh[wid] = r;
        __syncthreads();
        if (tid == 0) {
            float s = 0.f;
            #pragma unroll
            for (int w = 0; w < NWARP; w++) s += shh[w];
            g_p2[b][blk] = s;
        }
    }

    // ================= Finalize (last block globally) =================
    __shared__ int sh_fin;
    __threadfence();
    __syncthreads();
    if (tid == 0) sh_fin = (atomicAdd(&g_t2, 1) == GB - 1);
    __syncthreads();
    if (!sh_fin) return;

    __shared__ float fin[BB];
    if (tid < BB) {
        float s = 0.f;
        #pragma unroll
        for (int p = 0; p < BPB; p++) s += g_p2[tid][p];
        fin[tid] = s;
    }
    __syncthreads();
    if (tid == 0) {
        float var_tot = 0.f, wn = 0.f, cfg = 0.f;
        #pragma unroll
        for (int bb = 0; bb < BB; bb++) {
            float nlanes = 0.f;
            #pragma unroll
            for (int l = 0; l < NL; l++) {
                const float c = g_cnts[bb][l];
                if (c > 0.f) nlanes += 1.f;
                cfg += c;
            }
            var_tot += fin[bb] / fmaxf(nlanes, 1.f);
            wn += g_wnll[bb];
        }
        const float wsum = 0.5f * (float)(BB * NPIX) + 0.5f * cfg;
        // dist_loss == 0 identically (delta_d added to all pair distances);
        // reg_loss == 0.  loss = seg_ce + var.
        out[0] = wn / wsum + var_tot / (float)BB;
        // reset persistent state for the next graph replay
        #pragma unroll
        for (int bb = 0; bb < BB; bb++) { g_tb[bb] = 0; g_flag[bb] = 0; }
        g_t2 = 0;
    }
}

// ---------------------------------------------------------------------------
extern "C" void kernel_launch(void* const* d_in, const int* in_sizes, int n_in,
                              void* d_out, int out_size) {
    const float* emb  = (const float*)d_in[0];  // [16,4,288,800] f32
    const float* bseg = (const float*)d_in[1];  // [16,2,288,800] f32
    const int*   lab  = (const int*)  d_in[2];  // [16,288,800]   i32
    float* out = (float*)d_out;
    (void)in_sizes; (void)n_in; (void)out_size;

    cudaFuncSetAttribute(fused_kernel,
                         cudaFuncAttributeMaxDynamicSharedMemorySize, DYN_SMEM);
    dim3 grid(BPB, BB);
    fused_kernel<<<grid, TPB, DYN_SMEM>>>(emb, bseg, lab, out);
}